// round 16
// baseline (speedup 1.0000x reference)
#include <cuda_runtime.h>
#include <math.h>

#define NSIZE 96
#define MTOT  (NSIZE * NSIZE)        // 9216
#define GDIM  (2 * NSIZE - 1)        // 191
#define GTOT  (GDIM * GDIM)          // 36481
#define CHUNKS 32
#define CROWS  (NSIZE / CHUNKS)      // 3 source rows per chunk
#define AJT    16                    // aj values per block (2 per warp)
#define BJT    6                     // bj outputs per lane
#define GROWS  (CROWS + AJT - 1)     // 18 staged G rows
#define NBLOCKS ((NSIZE / AJT) * CHUNKS)   // 6 * 32 = 192
#define NTHREADS 256

// Physics constants (match reference)
#define WAVELEN 1.55e-6
#define DZ      1.0e-5
#define TWO_PI  6.283185307179586476925286766559
#define TWO_PI_F 6.2831853071795864769f
// (dz/lambda)^2 in extended precision
#define AZ2_F  41.62330905306972f

// Scratch in __device__ globals (no allocations allowed)
__device__ float4 d_modes4[MTOT];    // (mx, my, mx+my, 0)
__device__ float2 d_G[GTOT];         // (gx, gy)
__device__ float  d_part_re[CHUNKS * MTOT];
__device__ float  d_part_im[CHUNKS * MTOT];
__device__ unsigned g_ctr[2];        // monotonic barrier tickets (never reset)

// Grid-wide barrier, replay-safe: tickets are monotonic across launches.
__device__ __forceinline__ void grid_barrier(int i) {
    __syncthreads();
    if (threadIdx.x == 0) {
        __threadfence();
        unsigned ticket = atomicAdd(&g_ctr[i], 1u) + 1u;
        unsigned target = ((ticket + NBLOCKS - 1u) / NBLOCKS) * NBLOCKS;
        while (*(volatile unsigned*)&g_ctr[i] < target) { }
        __threadfence();
    }
    __syncthreads();
}

__global__ void __launch_bounds__(NTHREADS, 3)
fused_all(const float* __restrict__ x,
          const float* __restrict__ w,
          const float* __restrict__ xc,
          const float* __restrict__ yc,
          float* __restrict__ out, int out_size) {
    __shared__ __align__(16) float4 sm4[CROWS * NSIZE];  // modes (3x96)
    __shared__ __align__(16) float2 sg[GROWS * GDIM];    // G window (18x191)

    int tid = threadIdx.x;
    int bx  = blockIdx.x;

    // ---------------- Phase A: prep (all fp32) ---------------------------
    {
        int i = bx * NTHREADS + tid;
        if (i < MTOT) {
            float s, c;
            sincosf(w[i], &s, &c);
            float xv = x[i];
            float mr = xv * c, mi = xv * s;
            d_modes4[i] = make_float4(mr, mi, mr + mi, 0.f);
        } else if (i < 2 * MTOT) {
            int t = i - MTOT;
            int da = t / NSIZE;
            int db = t - da * NSIZE;

            const float inv_lam = (float)(1.0 / WAVELEN);
            float ax = (xc[da] - xc[0]) * inv_lam;
            float ay = (yc[db] - yc[0]) * inv_lam;
            float q  = fmaf(ax, ax, fmaf(ay, ay, AZ2_F));  // (r/lambda)^2

            // frac(sqrt(q)) with FMA-cancellation Newton refinement
            float s0 = sqrtf(q);
            float e  = fmaf(-s0, s0, q);
            float ds = e / (2.0f * s0);
            float frac = (s0 - truncf(s0)) + ds;
            float sn, cs;
            sincosf(TWO_PI_F * frac, &sn, &cs);

            float r2f  = q * (float)(WAVELEN * WAVELEN);
            float invr = rsqrtf(r2f);
            float inv_r2 = invr * invr;
            const float dAf = (float)(1.55e-6 * 1.55e-6);
            float ar = (float)(DZ / TWO_PI) * inv_r2 * invr;
            float ai = (float)(-DZ / WAVELEN) * inv_r2;
            float2 g = make_float2((ar * cs - ai * sn) * dAf,
                                   (ar * sn + ai * cs) * dAf);

            int rp = (NSIZE - 1) + da, rm = (NSIZE - 1) - da;
            int cp = (NSIZE - 1) + db, cm = (NSIZE - 1) - db;
            d_G[rp * GDIM + cp] = g;
            d_G[rp * GDIM + cm] = g;
            d_G[rm * GDIM + cp] = g;
            d_G[rm * GDIM + cm] = g;
        }
    }

    grid_barrier(0);

    // ---------------- Phase B: correlation, BJT=6 sliding window ---------
    // Karatsuba: A += mx*gx ; B += my*gy ; C += (mx+my)*(gx+gy)
    // re = A - B ; im = C - A - B
    // 8 warps/block; warp covers 2 aj rows (16 lanes each); each lane
    // computes 6 consecutive bj with a 6-deep G register window:
    // 1 LDS.64 + 1 broadcast serve 6 cMACs.
    {
        int ajb = bx % (NSIZE / AJT);        // 0..5
        int ch  = bx / (NSIZE / AJT);        // 0..31
        int aj0 = ajb * AJT;
        int ai0 = ch * CROWS;

        for (int t = tid; t < CROWS * NSIZE; t += NTHREADS)
            sm4[t] = d_modes4[ai0 * NSIZE + t];

        int row0 = ai0 - aj0 + (NSIZE - 1) - (AJT - 1);
        for (int t = tid; t < GROWS * GDIM; t += NTHREADS) {
            int ci = t / GDIM;
            int cc = t - ci * GDIM;
            sg[t] = d_G[(row0 + ci) * GDIM + cc];
        }
        __syncthreads();

        int ww    = tid >> 5;                // 0..7
        int lane  = tid & 31;
        int ajoff = ww * 2 + (lane >> 4);    // 0..15
        int p     = lane & 15;
        int bj0   = p * BJT;                 // 0, 6, ..., 90

        float A[BJT], B[BJT], C[BJT];
        #pragma unroll
        for (int k = 0; k < BJT; k++) { A[k] = 0.f; B[k] = 0.f; C[k] = 0.f; }

        #pragma unroll
        for (int ci = 0; ci < CROWS; ci++) {
            const float4* __restrict__ mrow = &sm4[ci * NSIZE];
            const float2* __restrict__ grow =
                &sg[(ci + (AJT - 1) - ajoff) * GDIM + (NSIZE - 1) - bj0];

            // 6-deep window: W[k] holds G at relative col -(k) for k=1..5
            float2 W[BJT];
            float  WS[BJT];
            #pragma unroll
            for (int k = 1; k < BJT; k++) {
                W[k] = grow[-k];             // col >= 0, always in range
                WS[k] = W[k].x + W[k].y;
            }

            #pragma unroll 6
            for (int bi = 0; bi < NSIZE; bi++) {
                float2 g0 = grow[bi];        // 1 LDS.64 per 6 cMACs
                float4 m  = mrow[bi];        // broadcast (mx,my,msum)
                float gs0 = g0.x + g0.y;
                A[0] = fmaf(m.x, g0.x, A[0]);
                B[0] = fmaf(m.y, g0.y, B[0]);
                C[0] = fmaf(m.z, gs0,  C[0]);
                #pragma unroll
                for (int k = 1; k < BJT; k++) {
                    A[k] = fmaf(m.x, W[k].x, A[k]);
                    B[k] = fmaf(m.y, W[k].y, B[k]);
                    C[k] = fmaf(m.z, WS[k],  C[k]);
                }
                // slide window (register renames under full unroll)
                #pragma unroll
                for (int k = BJT - 1; k > 1; k--) {
                    W[k] = W[k - 1]; WS[k] = WS[k - 1];
                }
                W[1] = g0; WS[1] = gs0;
            }
        }

        int base = ch * MTOT + (aj0 + ajoff) * NSIZE + bj0;
        #pragma unroll
        for (int k = 0; k < BJT; k++) {
            d_part_re[base + k] = A[k] - B[k];
            d_part_im[base + k] = C[k] - A[k] - B[k];
        }
    }

    grid_barrier(1);

    // ---------------- Phase C: reduce + format ---------------------------
    {
        int t = bx * NTHREADS + tid;
        if (out_size == 2 * MTOT) {
            if (t < 2 * MTOT) {
                const float* __restrict__ src =
                    (t < MTOT) ? d_part_re : d_part_im;
                int j = (t < MTOT) ? t : t - MTOT;
                float acc = 0.f;
                #pragma unroll
                for (int ch = 0; ch < CHUNKS; ch++)
                    acc += src[ch * MTOT + j];
                out[t] = acc;
            }
        } else if (out_size == MTOT) {
            if (t < MTOT) {
                float acc = 0.f;
                #pragma unroll
                for (int ch = 0; ch < CHUNKS; ch++)
                    acc += d_part_re[ch * MTOT + t];
                out[t] = acc;
            }
        } else {
            if (t < MTOT) {
                float re = 0.f, im = 0.f;
                #pragma unroll
                for (int ch = 0; ch < CHUNKS; ch++) {
                    re += d_part_re[ch * MTOT + t];
                    im += d_part_im[ch * MTOT + t];
                }
                ((float2*)out)[t] = make_float2(re, im);
            }
        }
    }
}

extern "C" void kernel_launch(void* const* d_in, const int* in_sizes, int n_in,
                              void* d_out, int out_size) {
    const float* x  = (const float*)d_in[0];
    const float* w  = (const float*)d_in[1];
    const float* xc = (const float*)d_in[2];
    const float* yc = (const float*)d_in[3];

    fused_all<<<NBLOCKS, NTHREADS>>>(x, w, xc, yc, (float*)d_out, out_size);
}

// round 17
// speedup vs baseline: 1.2670x; 1.2670x over previous
#include <cuda_runtime.h>
#include <math.h>

#define NSIZE 96
#define MTOT  (NSIZE * NSIZE)        // 9216
#define GDIM  (2 * NSIZE - 1)        // 191
#define GTOT  (GDIM * GDIM)          // 36481
#define CHUNKS 48
#define CROWS  (NSIZE / CHUNKS)      // 2 source rows per chunk
#define AJT    8                     // aj values per block (2 per warp)
#define BJT    6                     // bj outputs per lane
#define GROWS  (CROWS + AJT - 1)     // 9 staged G rows
#define NBLOCKS ((NSIZE / AJT) * CHUNKS)   // 12 * 48 = 576
#define NTHREADS 128

// Physics constants (match reference)
#define WAVELEN 1.55e-6
#define DZ      1.0e-5
#define TWO_PI  6.283185307179586476925286766559
#define TWO_PI_F 6.2831853071795864769f
// (dz/lambda)^2 in extended precision
#define AZ2_F  41.62330905306972f

// Scratch in __device__ globals (no allocations allowed)
__device__ float4 d_modes4[MTOT];    // (mx, my, mx+my, 0)
__device__ float2 d_G[GTOT];         // (gx, gy)
__device__ float  d_part_re[CHUNKS * MTOT];
__device__ float  d_part_im[CHUNKS * MTOT];
__device__ unsigned g_ctr[2];        // monotonic barrier tickets (never reset)

// Grid-wide barrier, replay-safe: tickets are monotonic across launches.
__device__ __forceinline__ void grid_barrier(int i) {
    __syncthreads();
    if (threadIdx.x == 0) {
        __threadfence();
        unsigned ticket = atomicAdd(&g_ctr[i], 1u) + 1u;
        unsigned target = ((ticket + NBLOCKS - 1u) / NBLOCKS) * NBLOCKS;
        while (*(volatile unsigned*)&g_ctr[i] < target) { }
        __threadfence();
    }
    __syncthreads();
}

__global__ void __launch_bounds__(NTHREADS, 6)
fused_all(const float* __restrict__ x,
          const float* __restrict__ w,
          const float* __restrict__ xc,
          const float* __restrict__ yc,
          float* __restrict__ out, int out_size) {
    __shared__ __align__(16) float4 sm4[CROWS * NSIZE];  // modes (2x96)
    __shared__ __align__(16) float2 sg[GROWS * GDIM];    // G window (9x191)

    int tid = threadIdx.x;
    int bx  = blockIdx.x;

    // ---------------- Phase A: prep (all fp32) ---------------------------
    {
        int i = bx * NTHREADS + tid;
        if (i < MTOT) {
            float s, c;
            sincosf(w[i], &s, &c);
            float xv = x[i];
            float mr = xv * c, mi = xv * s;
            d_modes4[i] = make_float4(mr, mi, mr + mi, 0.f);
        } else if (i < 2 * MTOT) {
            int t = i - MTOT;
            int da = t / NSIZE;
            int db = t - da * NSIZE;

            const float inv_lam = (float)(1.0 / WAVELEN);
            float ax = (xc[da] - xc[0]) * inv_lam;
            float ay = (yc[db] - yc[0]) * inv_lam;
            float q  = fmaf(ax, ax, fmaf(ay, ay, AZ2_F));  // (r/lambda)^2

            // frac(sqrt(q)) with FMA-cancellation Newton refinement
            float s0 = sqrtf(q);
            float e  = fmaf(-s0, s0, q);
            float ds = e / (2.0f * s0);
            float frac = (s0 - truncf(s0)) + ds;
            float sn, cs;
            sincosf(TWO_PI_F * frac, &sn, &cs);

            float r2f  = q * (float)(WAVELEN * WAVELEN);
            float invr = rsqrtf(r2f);
            float inv_r2 = invr * invr;
            const float dAf = (float)(1.55e-6 * 1.55e-6);
            float ar = (float)(DZ / TWO_PI) * inv_r2 * invr;
            float ai = (float)(-DZ / WAVELEN) * inv_r2;
            float2 g = make_float2((ar * cs - ai * sn) * dAf,
                                   (ar * sn + ai * cs) * dAf);

            int rp = (NSIZE - 1) + da, rm = (NSIZE - 1) - da;
            int cp = (NSIZE - 1) + db, cm = (NSIZE - 1) - db;
            d_G[rp * GDIM + cp] = g;
            d_G[rp * GDIM + cm] = g;
            d_G[rm * GDIM + cp] = g;
            d_G[rm * GDIM + cm] = g;
        }
    }

    grid_barrier(0);

    // ---------------- Phase B: correlation, BJT=6 sliding window ---------
    // Karatsuba: A += mx*gx ; B += my*gy ; C += (mx+my)*(gx+gy)
    // re = A - B ; im = C - A - B
    // Warp covers 2 aj rows (16 lanes each); each lane computes 6
    // consecutive bj with a 6-deep G register window: 1 LDS.64 + 1
    // broadcast serve 6 cMACs.
    {
        int ajb = bx % (NSIZE / AJT);        // 0..11
        int ch  = bx / (NSIZE / AJT);        // 0..47
        int aj0 = ajb * AJT;
        int ai0 = ch * CROWS;

        for (int t = tid; t < CROWS * NSIZE; t += NTHREADS)
            sm4[t] = d_modes4[ai0 * NSIZE + t];

        int row0 = ai0 - aj0 + (NSIZE - 1) - (AJT - 1);
        for (int t = tid; t < GROWS * GDIM; t += NTHREADS) {
            int ci = t / GDIM;
            int cc = t - ci * GDIM;
            sg[t] = d_G[(row0 + ci) * GDIM + cc];
        }
        __syncthreads();

        int ww    = tid >> 5;
        int lane  = tid & 31;
        int ajoff = ww * 2 + (lane >> 4);    // 0..7
        int p     = lane & 15;
        int bj0   = p * BJT;                 // 0, 6, ..., 90

        float A[BJT], B[BJT], C[BJT];
        #pragma unroll
        for (int k = 0; k < BJT; k++) { A[k] = 0.f; B[k] = 0.f; C[k] = 0.f; }

        #pragma unroll
        for (int ci = 0; ci < CROWS; ci++) {
            const float4* __restrict__ mrow = &sm4[ci * NSIZE];
            const float2* __restrict__ grow =
                &sg[(ci + (AJT - 1) - ajoff) * GDIM + (NSIZE - 1) - bj0];

            // 6-deep window: W[k] holds G at relative col -(k) for k=1..5
            float2 W[BJT];
            float  WS[BJT];
            #pragma unroll
            for (int k = 1; k < BJT; k++) {
                W[k] = grow[-k];             // col >= 0, always in range
                WS[k] = W[k].x + W[k].y;
            }

            #pragma unroll 6
            for (int bi = 0; bi < NSIZE; bi++) {
                float2 g0 = grow[bi];        // 1 LDS.64 per 6 cMACs
                float4 m  = mrow[bi];        // broadcast (mx,my,msum)
                float gs0 = g0.x + g0.y;
                A[0] = fmaf(m.x, g0.x, A[0]);
                B[0] = fmaf(m.y, g0.y, B[0]);
                C[0] = fmaf(m.z, gs0,  C[0]);
                #pragma unroll
                for (int k = 1; k < BJT; k++) {
                    A[k] = fmaf(m.x, W[k].x, A[k]);
                    B[k] = fmaf(m.y, W[k].y, B[k]);
                    C[k] = fmaf(m.z, WS[k],  C[k]);
                }
                // slide window (register renames under full unroll)
                #pragma unroll
                for (int k = BJT - 1; k > 1; k--) {
                    W[k] = W[k - 1]; WS[k] = WS[k - 1];
                }
                W[1] = g0; WS[1] = gs0;
            }
        }

        int base = ch * MTOT + (aj0 + ajoff) * NSIZE + bj0;
        #pragma unroll
        for (int k = 0; k < BJT; k++) {
            d_part_re[base + k] = A[k] - B[k];
            d_part_im[base + k] = C[k] - A[k] - B[k];
        }
    }

    grid_barrier(1);

    // ---------------- Phase C: reduce + format ---------------------------
    {
        int t = bx * NTHREADS + tid;
        if (out_size == 2 * MTOT) {
            if (t < 2 * MTOT) {
                const float* __restrict__ src =
                    (t < MTOT) ? d_part_re : d_part_im;
                int j = (t < MTOT) ? t : t - MTOT;
                float acc = 0.f;
                #pragma unroll
                for (int ch = 0; ch < CHUNKS; ch++)
                    acc += src[ch * MTOT + j];
                out[t] = acc;
            }
        } else if (out_size == MTOT) {
            if (t < MTOT) {
                float acc = 0.f;
                #pragma unroll
                for (int ch = 0; ch < CHUNKS; ch++)
                    acc += d_part_re[ch * MTOT + t];
                out[t] = acc;
            }
        } else {
            if (t < MTOT) {
                float re = 0.f, im = 0.f;
                #pragma unroll
                for (int ch = 0; ch < CHUNKS; ch++) {
                    re += d_part_re[ch * MTOT + t];
                    im += d_part_im[ch * MTOT + t];
                }
                ((float2*)out)[t] = make_float2(re, im);
            }
        }
    }
}

extern "C" void kernel_launch(void* const* d_in, const int* in_sizes, int n_in,
                              void* d_out, int out_size) {
    const float* x  = (const float*)d_in[0];
    const float* w  = (const float*)d_in[1];
    const float* xc = (const float*)d_in[2];
    const float* yc = (const float*)d_in[3];

    fused_all<<<NBLOCKS, NTHREADS>>>(x, w, xc, yc, (float*)d_out, out_size);
}